// round 1
// baseline (speedup 1.0000x reference)
#include <cuda_runtime.h>
#include <math.h>

// ---------------- problem constants ----------------
constexpr int Bc   = 2;
constexpr int Sc   = 2048;
constexpr int Hc   = 2048;
constexpr int Tc   = Bc * Sc;      // 4096 tokens
constexpr int Ec   = 8;
constexpr int KTOP = 4;
constexpr int IM   = 1408;
constexpr int ISH  = 5632;
constexpr int NQc  = 16;
constexpr int NKVc = 2;
constexpr int DHc  = 128;
constexpr float EPSc = 1e-5f;

// ---------------- scratch (device globals; no allocations allowed) ----------------
__device__ float g_h  [(size_t)Tc * Hc];            // rms1 output
__device__ float g_q  [(size_t)Tc * NQc * DHc];     // q (post bias+rope)
__device__ float g_k  [(size_t)Tc * NKVc * DHc];
__device__ float g_v  [(size_t)Tc * NKVc * DHc];
__device__ float g_kT [(size_t)Bc * NKVc * DHc * Sc]; // K transposed per (b,kv): [bk][d][s]
__device__ float g_sc [(size_t)Bc * NQc * Sc * Sc];   // scores -> probs (in place), 536MB
__device__ float g_ao [(size_t)Tc * Hc];            // attention out (pre O-proj)
__device__ float g_x  [(size_t)Tc * Hc];            // residual after attention
__device__ float g_t2 [(size_t)Tc * Hc];            // rms2 output
__device__ float g_dw [Tc * Ec];                    // dense router weights
__device__ int   g_cnt[Ec];
__device__ int   g_list[Ec * Tc];
__device__ float g_mg [(size_t)Ec * Tc * IM];       // expert gate buf (then act)
__device__ float g_mu [(size_t)Ec * Tc * IM];       // expert up buf
__device__ float g_moe[(size_t)Tc * Hc];            // moe accumulation
__device__ float g_sgv[(size_t)Tc * ISH];           // shared gate buf (then act)
__device__ float g_suv[(size_t)Tc * ISH];           // shared up buf
__device__ float g_sh [(size_t)Tc * Hc];            // shared expert down output
__device__ float g_sgate[Tc];                       // sigmoid gate scalar per token

// ---------------- small kernels ----------------
__global__ void clear_cnt_kernel() {
    if (threadIdx.x < Ec) g_cnt[threadIdx.x] = 0;
}
__global__ void clear_moe_kernel() {
    g_moe[(size_t)blockIdx.x * 256 + threadIdx.x] = 0.f;
}

template<int PHASE>
__global__ void rmsnorm_kernel(const float* __restrict__ xin,
                               const float* __restrict__ scale) {
    __shared__ float red[256];
    const int row = blockIdx.x;
    const float* x = (PHASE == 0) ? (xin + (size_t)row * Hc) : (g_x + (size_t)row * Hc);
    float* out = (PHASE == 0) ? (g_h + (size_t)row * Hc) : (g_t2 + (size_t)row * Hc);
    float s = 0.f;
    for (int i = threadIdx.x; i < Hc; i += 256) { float v = x[i]; s += v * v; }
    red[threadIdx.x] = s; __syncthreads();
    for (int o = 128; o > 0; o >>= 1) {
        if (threadIdx.x < o) red[threadIdx.x] += red[threadIdx.x + o];
        __syncthreads();
    }
    const float inv = rsqrtf(red[0] / (float)Hc + EPSc);
    for (int i = threadIdx.x; i < Hc; i += 256) out[i] = x[i] * inv * scale[i];
}

// RoPE (half-split) applied in place to q (heads 0..15) and k (heads 16..17)
__global__ void rope_kernel() {
    const int tok  = blockIdx.x;
    const int head = blockIdx.y;
    const int j    = threadIdx.x;         // 0..63
    const int s    = tok & (Sc - 1);
    const float inv = powf(10000.f, -(float)(2 * j) / 128.f);
    const float ang = (float)s * inv;
    float si, c;
    sincosf(ang, &si, &c);
    float* p = (head < NQc) ? (g_q + (size_t)tok * (NQc * DHc) + head * DHc)
                            : (g_k + (size_t)tok * (NKVc * DHc) + (head - NQc) * DHc);
    const float x1 = p[j], x2 = p[j + 64];
    p[j]      = x1 * c - x2 * si;
    p[j + 64] = x2 * c + x1 * si;
}

// kT[bk][d][s] = k[b*S+s][kv*128+d]
__global__ void kT_kernel() {
    const int i  = blockIdx.x * 256 + threadIdx.x;   // < B*NKV*128*2048 = 1048576
    const int s  = i & (Sc - 1);
    const int d  = (i >> 11) & 127;
    const int bk = i >> 18;
    g_kT[i] = g_k[((size_t)((bk >> 1) * Sc + s)) * (NKVc * DHc) + (bk & 1) * DHc + d];
}

// in-place causal softmax per row (scores already scaled, masked cols never read)
__global__ void softmax_kernel() {
    __shared__ float red[256];
    const size_t rid = blockIdx.x;        // 0 .. B*NQ*S-1
    const int r   = (int)(rid & (Sc - 1));
    float* sc = g_sc + rid * Sc;
    const int lim = r + 1;
    const int tid = threadIdx.x;
    float m = -1e30f;
    for (int c = tid; c < lim; c += 256) m = fmaxf(m, sc[c]);
    red[tid] = m; __syncthreads();
    for (int o = 128; o > 0; o >>= 1) {
        if (tid < o) red[tid] = fmaxf(red[tid], red[tid + o]);
        __syncthreads();
    }
    m = red[0]; __syncthreads();
    float s = 0.f;
    for (int c = tid; c < lim; c += 256) s += expf(sc[c] - m);
    red[tid] = s; __syncthreads();
    for (int o = 128; o > 0; o >>= 1) {
        if (tid < o) red[tid] += red[tid + o];
        __syncthreads();
    }
    const float inv = 1.f / red[0];
    for (int c = tid; c < Sc; c += 256)
        sc[c] = (c < lim) ? expf(sc[c] - m) * inv : 0.f;
}

// router: logits -> softmax(8) -> top4 -> normalized dense weights + expert lists
__global__ void router_kernel(const float* __restrict__ rw) {
    const int tok  = blockIdx.x * 8 + (threadIdx.x >> 5);
    const int lane = threadIdx.x & 31;
    const float* tr = g_t2 + (size_t)tok * Hc;
    float acc[8];
#pragma unroll
    for (int e = 0; e < 8; e++) acc[e] = 0.f;
    for (int h = lane; h < Hc; h += 32) {
        const float tv = tr[h];
        const float* rp = rw + h * 8;
#pragma unroll
        for (int e = 0; e < 8; e++) acc[e] += tv * rp[e];
    }
#pragma unroll
    for (int e = 0; e < 8; e++)
        for (int o = 16; o; o >>= 1) acc[e] += __shfl_xor_sync(0xffffffffu, acc[e], o);
    if (lane == 0) {
        float m = acc[0];
        for (int e = 1; e < 8; e++) m = fmaxf(m, acc[e]);
        float p[8], s = 0.f;
        for (int e = 0; e < 8; e++) { p[e] = expf(acc[e] - m); s += p[e]; }
        for (int e = 0; e < 8; e++) p[e] /= s;
        bool used[8] = {false,false,false,false,false,false,false,false};
        int isel[4]; float wsel[4]; float tsum = 0.f;
        for (int kk = 0; kk < 4; kk++) {
            int best = 0; float bv = -1.f;
            for (int e = 0; e < 8; e++)
                if (!used[e] && p[e] > bv) { bv = p[e]; best = e; }
            used[best] = true; isel[kk] = best; wsel[kk] = bv; tsum += bv;
        }
        float outw[8] = {0,0,0,0,0,0,0,0};
        for (int kk = 0; kk < 4; kk++) outw[isel[kk]] = wsel[kk] / tsum;
        for (int e = 0; e < 8; e++) g_dw[tok * 8 + e] = outw[e];
        for (int kk = 0; kk < 4; kk++) {
            const int pos = atomicAdd(&g_cnt[isel[kk]], 1);
            g_list[isel[kk] * Tc + pos] = tok;
        }
    }
}

// silu(gate)*up for MoE experts (bounded by per-expert count), in place into g_mg
__global__ void moe_act_kernel() {
    const int e = blockIdx.z, row = blockIdx.y;
    if (row >= g_cnt[e]) return;
    const int col = blockIdx.x * 256 + threadIdx.x;
    if (col >= IM) return;
    const size_t i = ((size_t)e * Tc + row) * IM + col;
    const float g = g_mg[i], u = g_mu[i];
    g_mg[i] = g / (1.f + expf(-g)) * u;
}

__global__ void shared_act_kernel() {
    const size_t i = (size_t)blockIdx.x * 256 + threadIdx.x;
    const float g = g_sgv[i], u = g_suv[i];
    g_sgv[i] = g / (1.f + expf(-g)) * u;
}

__global__ void sgate_kernel(const float* __restrict__ sgw) {
    const int tok  = blockIdx.x * 8 + (threadIdx.x >> 5);
    const int lane = threadIdx.x & 31;
    const float* tr = g_t2 + (size_t)tok * Hc;
    float s = 0.f;
    for (int h = lane; h < Hc; h += 32) s += tr[h] * sgw[h];
    for (int o = 16; o; o >>= 1) s += __shfl_xor_sync(0xffffffffu, s, o);
    if (lane == 0) g_sgate[tok] = 1.f / (1.f + expf(-s));
}

__global__ void final_kernel(float* __restrict__ out) {
    const size_t i = (size_t)blockIdx.x * 256 + threadIdx.x;
    const int row = (int)(i >> 11);   // H = 2048
    out[i] = g_x[i] + g_moe[i] + g_sgate[row] * g_sh[i];
}

// ---------------- the one SGEMM to rule them all ----------------
enum GMode { GM_Q, GM_K, GM_V, GM_SCORES, GM_PV, GM_O,
             GM_MG, GM_MU, GM_MD, GM_SG, GM_SU, GM_SD };

template<int MODE>
__global__ __launch_bounds__(256) void gemm_kernel(const float* __restrict__ W,
                                                   const float* __restrict__ extra) {
    constexpr int Nv =
        (MODE==GM_Q || MODE==GM_O || MODE==GM_MD || MODE==GM_SD) ? 2048 :
        (MODE==GM_K || MODE==GM_V) ? 256 :
        (MODE==GM_SCORES) ? Sc :
        (MODE==GM_PV) ? 128 :
        (MODE==GM_MG || MODE==GM_MU) ? IM : ISH;
    (void)Nv;
    constexpr int Kv =
        (MODE==GM_SCORES) ? 128 :
        (MODE==GM_PV) ? Sc :
        (MODE==GM_MD) ? IM :
        (MODE==GM_SD) ? ISH : 2048;

    const int tid = threadIdx.x;
    const int z   = blockIdx.z;
    const int m0  = blockIdx.y * 128, n0 = blockIdx.x * 128;

    int Mz;
    if (MODE==GM_SCORES || MODE==GM_PV) Mz = Sc;
    else if (MODE==GM_MG || MODE==GM_MU || MODE==GM_MD) Mz = g_cnt[z];
    else Mz = Tc;
    if (m0 >= Mz) return;
    if (MODE==GM_SCORES && n0 > m0 + 127) return;   // fully masked tile

    int bb = 0, hh = 0;
    if (MODE==GM_SCORES || MODE==GM_PV) { bb = z >> 4; hh = z & 15; }

    const float* A; const float* Bp; int lda, ldb;
    if (MODE==GM_Q || MODE==GM_K || MODE==GM_V) {
        A = g_h; lda = Hc; Bp = W; ldb = (MODE==GM_Q) ? 2048 : 256;
    } else if (MODE==GM_SCORES) {
        A = g_q + (size_t)bb * Sc * 2048 + hh * 128; lda = 2048;
        Bp = g_kT + (size_t)(bb * 2 + (hh >> 3)) * 128 * Sc; ldb = Sc;
    } else if (MODE==GM_PV) {
        A = g_sc + (size_t)z * Sc * Sc; lda = Sc;
        Bp = g_v + (size_t)bb * Sc * 256 + (hh >> 3) * 128; ldb = 256;
    } else if (MODE==GM_O) {
        A = g_ao; lda = 2048; Bp = W; ldb = 2048;
    } else if (MODE==GM_MG || MODE==GM_MU) {
        A = g_t2; lda = 2048; Bp = W + (size_t)z * 2048 * IM; ldb = IM;
    } else if (MODE==GM_MD) {
        A = g_mg + (size_t)z * Tc * IM; lda = IM;
        Bp = W + (size_t)z * IM * 2048; ldb = 2048;
    } else if (MODE==GM_SG || MODE==GM_SU) {
        A = g_t2; lda = 2048; Bp = W; ldb = ISH;
    } else { // GM_SD
        A = g_sgv; lda = ISH; Bp = W; ldb = 2048;
    }

    __shared__ float As[8][128];
    __shared__ float Bs[8][128];
    float acc[64];
#pragma unroll
    for (int i = 0; i < 64; i++) acc[i] = 0.f;

    const int arow = tid >> 1, acol = (tid & 1) * 4;
    const int brow = tid >> 5, bcol = (tid & 31) * 4;
    const int agl  = m0 + arow;
    const bool aval = agl < Mz;
    const float* arp;
    if (MODE==GM_MG || MODE==GM_MU)
        arp = aval ? (A + (size_t)g_list[z * Tc + agl] * lda) : A;
    else
        arp = A + (size_t)agl * lda;
    const float* brp = Bp + n0 + bcol;
    const int tx = tid & 15, ty = tid >> 4;

    for (int k0 = 0; k0 < Kv; k0 += 8) {
        float4 av = make_float4(0.f, 0.f, 0.f, 0.f);
        if (aval) av = *(const float4*)(arp + k0 + acol);
        const float4 bv = *(const float4*)(brp + (size_t)(k0 + brow) * ldb);
        As[acol + 0][arow] = av.x; As[acol + 1][arow] = av.y;
        As[acol + 2][arow] = av.z; As[acol + 3][arow] = av.w;
        *(float4*)(&Bs[brow][bcol]) = bv;
        __syncthreads();
#pragma unroll
        for (int kk = 0; kk < 8; kk++) {
            const float4 a0 = *(const float4*)(&As[kk][ty * 8]);
            const float4 a1 = *(const float4*)(&As[kk][ty * 8 + 4]);
            const float4 b0 = *(const float4*)(&Bs[kk][tx * 8]);
            const float4 b1 = *(const float4*)(&Bs[kk][tx * 8 + 4]);
            const float ar[8] = {a0.x,a0.y,a0.z,a0.w,a1.x,a1.y,a1.z,a1.w};
            const float br[8] = {b0.x,b0.y,b0.z,b0.w,b1.x,b1.y,b1.z,b1.w};
#pragma unroll
            for (int i = 0; i < 8; i++)
#pragma unroll
                for (int j = 0; j < 8; j++)
                    acc[i * 8 + j] = fmaf(ar[i], br[j], acc[i * 8 + j]);
        }
        __syncthreads();
    }

    // ---------------- epilogues ----------------
    const float scl = 0.08838834764831845f;  // 1/sqrt(128)
#pragma unroll
    for (int i = 0; i < 8; i++) {
        const int r = m0 + ty * 8 + i;
        if (r >= Mz) continue;
        if (MODE==GM_SCORES) {
            const size_t base = (size_t)z * Sc * Sc + (size_t)r * Sc;
#pragma unroll
            for (int j = 0; j < 8; j++) {
                const int c = n0 + tx * 8 + j;
                float v = acc[i * 8 + j] * scl;
                if (c > r) v = -1e9f;
                g_sc[base + c] = v;
            }
        } else if (MODE==GM_MD) {
            const int tok = g_list[z * Tc + r];
            const float w = g_dw[tok * Ec + z];
            float* dst = g_moe + (size_t)tok * 2048 + n0 + tx * 8;
#pragma unroll
            for (int j = 0; j < 8; j++) atomicAdd(dst + j, acc[i * 8 + j] * w);
        } else {
            float* Cp; int ldc; const float* bias = nullptr; const float* res = nullptr;
            if (MODE==GM_Q)       { Cp = g_q;  ldc = 2048; bias = extra; }
            else if (MODE==GM_K)  { Cp = g_k;  ldc = 256;  bias = extra; }
            else if (MODE==GM_V)  { Cp = g_v;  ldc = 256;  bias = extra; }
            else if (MODE==GM_PV) { Cp = g_ao + (size_t)bb * Sc * 2048 + hh * 128; ldc = 2048; }
            else if (MODE==GM_O)  { Cp = g_x;  ldc = 2048; res = extra; }
            else if (MODE==GM_MG) { Cp = g_mg + (size_t)z * Tc * IM; ldc = IM; }
            else if (MODE==GM_MU) { Cp = g_mu + (size_t)z * Tc * IM; ldc = IM; }
            else if (MODE==GM_SG) { Cp = g_sgv; ldc = ISH; }
            else if (MODE==GM_SU) { Cp = g_suv; ldc = ISH; }
            else                  { Cp = g_sh;  ldc = 2048; }
            const size_t rowoff = (size_t)r * ldc;
#pragma unroll
            for (int j = 0; j < 8; j++) {
                const int c = n0 + tx * 8 + j;
                float v = acc[i * 8 + j];
                if (bias) v += bias[c];
                if (res)  v += res[rowoff + c];
                Cp[rowoff + c] = v;
            }
        }
    }
}

// ---------------- launch ----------------
extern "C" void kernel_launch(void* const* d_in, const int* in_sizes, int n_in,
                              void* d_out, int out_size) {
    (void)in_sizes; (void)n_in; (void)out_size;
    const float* x0  = (const float*)d_in[0];
    const float* ln1 = (const float*)d_in[1];
    const float* wq  = (const float*)d_in[2];
    const float* bq  = (const float*)d_in[3];
    const float* wk  = (const float*)d_in[4];
    const float* bk  = (const float*)d_in[5];
    const float* wv  = (const float*)d_in[6];
    const float* bv  = (const float*)d_in[7];
    const float* wo  = (const float*)d_in[8];
    const float* ln2 = (const float*)d_in[9];
    const float* rw  = (const float*)d_in[10];
    const float* wg  = (const float*)d_in[11];
    const float* wu  = (const float*)d_in[12];
    const float* wd  = (const float*)d_in[13];
    const float* swg = (const float*)d_in[14];
    const float* swu = (const float*)d_in[15];
    const float* swd = (const float*)d_in[16];
    const float* sgw = (const float*)d_in[17];
    float* out = (float*)d_out;

    clear_cnt_kernel<<<1, 32>>>();
    clear_moe_kernel<<<(Tc * Hc) / 256, 256>>>();

    // attention
    rmsnorm_kernel<0><<<Tc, 256>>>(x0, ln1);
    gemm_kernel<GM_Q><<<dim3(16, 32, 1), 256>>>(wq, bq);
    gemm_kernel<GM_K><<<dim3(2, 32, 1), 256>>>(wk, bk);
    gemm_kernel<GM_V><<<dim3(2, 32, 1), 256>>>(wv, bv);
    rope_kernel<<<dim3(Tc, NQc + NKVc), 64>>>();
    kT_kernel<<<(Bc * NKVc * DHc * Sc) / 256, 256>>>();
    gemm_kernel<GM_SCORES><<<dim3(16, 16, 32), 256>>>(nullptr, nullptr);
    softmax_kernel<<<Bc * NQc * Sc, 256>>>();
    gemm_kernel<GM_PV><<<dim3(1, 16, 32), 256>>>(nullptr, nullptr);
    gemm_kernel<GM_O><<<dim3(16, 32, 1), 256>>>(wo, x0);

    // MoE block
    rmsnorm_kernel<1><<<Tc, 256>>>(nullptr, ln2);
    router_kernel<<<Tc / 8, 256>>>(rw);
    gemm_kernel<GM_MG><<<dim3(11, 32, 8), 256>>>(wg, nullptr);
    gemm_kernel<GM_MU><<<dim3(11, 32, 8), 256>>>(wu, nullptr);
    moe_act_kernel<<<dim3(6, Tc, 8), 256>>>();
    gemm_kernel<GM_MD><<<dim3(16, 32, 8), 256>>>(wd, nullptr);

    // shared expert
    gemm_kernel<GM_SG><<<dim3(44, 32, 1), 256>>>(swg, nullptr);
    gemm_kernel<GM_SU><<<dim3(44, 32, 1), 256>>>(swu, nullptr);
    shared_act_kernel<<<(size_t)(Tc) * ISH / 256, 256>>>();
    sgate_kernel<<<Tc / 8, 256>>>(sgw);
    gemm_kernel<GM_SD><<<dim3(16, 32, 1), 256>>>(swd, nullptr);

    final_kernel<<<(Tc * Hc) / 256, 256>>>(out);
}

// round 2
// speedup vs baseline: 2.6217x; 2.6217x over previous
#include <cuda_runtime.h>
#include <math.h>
#include <stdint.h>

// ---------------- problem constants ----------------
constexpr int Bc   = 2;
constexpr int Sc   = 2048;
constexpr int Hc   = 2048;
constexpr int Tc   = Bc * Sc;      // 4096 tokens
constexpr int Ec   = 8;
constexpr int IM   = 1408;
constexpr int ISH  = 5632;
constexpr int NQc  = 16;
constexpr int NKVc = 2;
constexpr int DHc  = 128;
constexpr float EPSc = 1e-5f;

// ---------------- scratch (device globals; no allocations allowed) ----------------
__device__ float g_h  [(size_t)Tc * Hc];
__device__ float g_q  [(size_t)Tc * NQc * DHc];
__device__ float g_k  [(size_t)Tc * NKVc * DHc];
__device__ float g_v  [(size_t)Tc * NKVc * DHc];
__device__ float g_kT [(size_t)Bc * NKVc * DHc * Sc];
__device__ float g_sc [(size_t)Bc * NQc * Sc * Sc];   // scores -> probs in place
__device__ float g_ao [(size_t)Tc * Hc];
__device__ float g_x  [(size_t)Tc * Hc];
__device__ float g_t2 [(size_t)Tc * Hc];
__device__ float g_dw [Tc * Ec];
__device__ int   g_cnt[Ec];
__device__ int   g_list[Ec * Tc];
__device__ float g_mg [(size_t)Ec * Tc * IM];
__device__ float g_mu [(size_t)Ec * Tc * IM];
__device__ float g_moe[(size_t)Tc * Hc];
__device__ float g_sgv[(size_t)Tc * ISH];
__device__ float g_suv[(size_t)Tc * ISH];
__device__ float g_sh [(size_t)Tc * Hc];
__device__ float g_sgate[Tc];

// ---------------- small kernels ----------------
__global__ void clear_cnt_kernel() {
    if (threadIdx.x < Ec) g_cnt[threadIdx.x] = 0;
}
__global__ void clear_moe_kernel() {
    g_moe[(size_t)blockIdx.x * 256 + threadIdx.x] = 0.f;
}

template<int PHASE>
__global__ void rmsnorm_kernel(const float* __restrict__ xin,
                               const float* __restrict__ scale) {
    __shared__ float red[256];
    const int row = blockIdx.x;
    const float* x = (PHASE == 0) ? (xin + (size_t)row * Hc) : (g_x + (size_t)row * Hc);
    float* out = (PHASE == 0) ? (g_h + (size_t)row * Hc) : (g_t2 + (size_t)row * Hc);
    float s = 0.f;
    for (int i = threadIdx.x; i < Hc; i += 256) { float v = x[i]; s += v * v; }
    red[threadIdx.x] = s; __syncthreads();
    for (int o = 128; o > 0; o >>= 1) {
        if (threadIdx.x < o) red[threadIdx.x] += red[threadIdx.x + o];
        __syncthreads();
    }
    const float inv = rsqrtf(red[0] / (float)Hc + EPSc);
    for (int i = threadIdx.x; i < Hc; i += 256) out[i] = x[i] * inv * scale[i];
}

__global__ void rope_kernel() {
    const int tok  = blockIdx.x;
    const int head = blockIdx.y;
    const int j    = threadIdx.x;         // 0..63
    const int s    = tok & (Sc - 1);
    const float inv = powf(10000.f, -(float)(2 * j) / 128.f);
    const float ang = (float)s * inv;
    float si, c;
    sincosf(ang, &si, &c);
    float* p = (head < NQc) ? (g_q + (size_t)tok * (NQc * DHc) + head * DHc)
                            : (g_k + (size_t)tok * (NKVc * DHc) + (head - NQc) * DHc);
    const float x1 = p[j], x2 = p[j + 64];
    p[j]      = x1 * c - x2 * si;
    p[j + 64] = x2 * c + x1 * si;
}

__global__ void kT_kernel() {
    const int i  = blockIdx.x * 256 + threadIdx.x;
    const int s  = i & (Sc - 1);
    const int d  = (i >> 11) & 127;
    const int bk = i >> 18;
    g_kT[i] = g_k[((size_t)((bk >> 1) * Sc + s)) * (NKVc * DHc) + (bk & 1) * DHc + d];
}

__global__ void softmax_kernel() {
    __shared__ float red[256];
    const size_t rid = blockIdx.x;
    const int r   = (int)(rid & (Sc - 1));
    float* sc = g_sc + rid * Sc;
    const int lim = r + 1;
    const int tid = threadIdx.x;
    float m = -1e30f;
    for (int c = tid; c < lim; c += 256) m = fmaxf(m, sc[c]);
    red[tid] = m; __syncthreads();
    for (int o = 128; o > 0; o >>= 1) {
        if (tid < o) red[tid] = fmaxf(red[tid], red[tid + o]);
        __syncthreads();
    }
    m = red[0]; __syncthreads();
    float s = 0.f;
    for (int c = tid; c < lim; c += 256) s += expf(sc[c] - m);
    red[tid] = s; __syncthreads();
    for (int o = 128; o > 0; o >>= 1) {
        if (tid < o) red[tid] += red[tid + o];
        __syncthreads();
    }
    const float inv = 1.f / red[0];
    for (int c = tid; c < Sc; c += 256)
        sc[c] = (c < lim) ? expf(sc[c] - m) * inv : 0.f;
}

__global__ void router_kernel(const float* __restrict__ rw) {
    const int tok  = blockIdx.x * 8 + (threadIdx.x >> 5);
    const int lane = threadIdx.x & 31;
    const float* tr = g_t2 + (size_t)tok * Hc;
    float acc[8];
#pragma unroll
    for (int e = 0; e < 8; e++) acc[e] = 0.f;
    for (int h = lane; h < Hc; h += 32) {
        const float tv = tr[h];
        const float* rp = rw + h * 8;
#pragma unroll
        for (int e = 0; e < 8; e++) acc[e] += tv * rp[e];
    }
#pragma unroll
    for (int e = 0; e < 8; e++)
        for (int o = 16; o; o >>= 1) acc[e] += __shfl_xor_sync(0xffffffffu, acc[e], o);
    if (lane == 0) {
        float m = acc[0];
        for (int e = 1; e < 8; e++) m = fmaxf(m, acc[e]);
        float p[8], s = 0.f;
        for (int e = 0; e < 8; e++) { p[e] = expf(acc[e] - m); s += p[e]; }
        for (int e = 0; e < 8; e++) p[e] /= s;
        bool used[8] = {false,false,false,false,false,false,false,false};
        int isel[4]; float wsel[4]; float tsum = 0.f;
        for (int kk = 0; kk < 4; kk++) {
            int best = 0; float bv = -1.f;
            for (int e = 0; e < 8; e++)
                if (!used[e] && p[e] > bv) { bv = p[e]; best = e; }
            used[best] = true; isel[kk] = best; wsel[kk] = bv; tsum += bv;
        }
        float outw[8] = {0,0,0,0,0,0,0,0};
        for (int kk = 0; kk < 4; kk++) outw[isel[kk]] = wsel[kk] / tsum;
        for (int e = 0; e < 8; e++) g_dw[tok * 8 + e] = outw[e];
        for (int kk = 0; kk < 4; kk++) {
            const int pos = atomicAdd(&g_cnt[isel[kk]], 1);
            g_list[isel[kk] * Tc + pos] = tok;
        }
    }
}

__global__ void moe_act_kernel() {
    const int e = blockIdx.z, row = blockIdx.y;
    if (row >= g_cnt[e]) return;
    const int col = blockIdx.x * 256 + threadIdx.x;
    if (col >= IM) return;
    const size_t i = ((size_t)e * Tc + row) * IM + col;
    const float g = g_mg[i], u = g_mu[i];
    g_mg[i] = g / (1.f + expf(-g)) * u;
}

__global__ void shared_act_kernel() {
    const size_t i = (size_t)blockIdx.x * 256 + threadIdx.x;
    const float g = g_sgv[i], u = g_suv[i];
    g_sgv[i] = g / (1.f + expf(-g)) * u;
}

__global__ void sgate_kernel(const float* __restrict__ sgw) {
    const int tok  = blockIdx.x * 8 + (threadIdx.x >> 5);
    const int lane = threadIdx.x & 31;
    const float* tr = g_t2 + (size_t)tok * Hc;
    float s = 0.f;
    for (int h = lane; h < Hc; h += 32) s += tr[h] * sgw[h];
    for (int o = 16; o; o >>= 1) s += __shfl_xor_sync(0xffffffffu, s, o);
    if (lane == 0) g_sgate[tok] = 1.f / (1.f + expf(-s));
}

__global__ void final_kernel(float* __restrict__ out) {
    const size_t i = (size_t)blockIdx.x * 256 + threadIdx.x;
    const int row = (int)(i >> 11);
    out[i] = g_x[i] + g_moe[i] + g_sgate[row] * g_sh[i];
}

// ---------------- tf32 tensor-core universal GEMM ----------------
enum GMode { GM_Q, GM_K, GM_V, GM_SCORES, GM_PV, GM_O,
             GM_MG, GM_MU, GM_MD, GM_SG, GM_SU, GM_SD };

__device__ __forceinline__ uint32_t f2tf(float x) {
    uint32_t r;
    asm("cvt.rna.tf32.f32 %0, %1;" : "=r"(r) : "f"(x));
    return r;
}

__device__ __forceinline__ void mma_tf32(float* c, const uint32_t* a, const uint32_t* b) {
    asm volatile(
        "mma.sync.aligned.m16n8k8.row.col.f32.tf32.tf32.f32 "
        "{%0,%1,%2,%3}, {%4,%5,%6,%7}, {%8,%9}, {%0,%1,%2,%3};"
        : "+f"(c[0]), "+f"(c[1]), "+f"(c[2]), "+f"(c[3])
        : "r"(a[0]), "r"(a[1]), "r"(a[2]), "r"(a[3]), "r"(b[0]), "r"(b[1]));
}

// BM=128, BN=128, BK=16; 256 threads = 8 warps (2 x 4), warp tile 64x32.
template<int MODE>
__global__ __launch_bounds__(256) void gemm_kernel(const float* __restrict__ W,
                                                   const float* __restrict__ extra) {
    constexpr int Kv =
        (MODE==GM_SCORES) ? 128 :
        (MODE==GM_PV) ? Sc :
        (MODE==GM_MD) ? IM :
        (MODE==GM_SD) ? ISH : 2048;

    const int tid = threadIdx.x;
    const int z   = blockIdx.z;
    const int m0  = blockIdx.y * 128, n0 = blockIdx.x * 128;

    int Mz;
    if (MODE==GM_SCORES || MODE==GM_PV) Mz = Sc;
    else if (MODE==GM_MG || MODE==GM_MU || MODE==GM_MD) Mz = g_cnt[z];
    else Mz = Tc;
    if (m0 >= Mz) return;
    if (MODE==GM_SCORES && n0 > m0 + 127) return;   // fully masked tile

    int bb = 0, hh = 0;
    if (MODE==GM_SCORES || MODE==GM_PV) { bb = z >> 4; hh = z & 15; }

    const float* A; const float* Bp; int lda, ldb;
    if (MODE==GM_Q || MODE==GM_K || MODE==GM_V) {
        A = g_h; lda = Hc; Bp = W; ldb = (MODE==GM_Q) ? 2048 : 256;
    } else if (MODE==GM_SCORES) {
        A = g_q + (size_t)bb * Sc * 2048 + hh * 128; lda = 2048;
        Bp = g_kT + (size_t)(bb * 2 + (hh >> 3)) * 128 * Sc; ldb = Sc;
    } else if (MODE==GM_PV) {
        A = g_sc + (size_t)z * Sc * Sc; lda = Sc;
        Bp = g_v + (size_t)bb * Sc * 256 + (hh >> 3) * 128; ldb = 256;
    } else if (MODE==GM_O) {
        A = g_ao; lda = 2048; Bp = W; ldb = 2048;
    } else if (MODE==GM_MG || MODE==GM_MU) {
        A = g_t2; lda = 2048; Bp = W + (size_t)z * 2048 * IM; ldb = IM;
    } else if (MODE==GM_MD) {
        A = g_mg + (size_t)z * Tc * IM; lda = IM;
        Bp = W + (size_t)z * IM * 2048; ldb = 2048;
    } else if (MODE==GM_SG || MODE==GM_SU) {
        A = g_t2; lda = 2048; Bp = W; ldb = ISH;
    } else { // GM_SD
        A = g_sgv; lda = ISH; Bp = W; ldb = 2048;
    }

    // smem: A transposed [k][m], B [k][n]; stride 136 -> conflict-free fragment LDS
    __shared__ uint32_t As[16][136];
    __shared__ uint32_t Bs[16][136];

    float acc[4][4][4];
#pragma unroll
    for (int i = 0; i < 4; i++)
#pragma unroll
        for (int j = 0; j < 4; j++)
#pragma unroll
            for (int r = 0; r < 4; r++) acc[i][j][r] = 0.f;

    const int lane = tid & 31, wid = tid >> 5;
    const int wm = (wid >> 2) * 64;     // warp row offset (0 / 64)
    const int wn = (wid & 3) * 32;      // warp col offset (0/32/64/96)

    // loader indices
    const int lm = tid >> 1, lk = (tid & 1) * 8;        // A: row lm, k chunk lk
    const int bkr = tid >> 4, bnc = (tid & 15) * 4;     // B: row bkr, col chunk bnc

    const int agl  = m0 + lm;
    const bool aval = agl < Mz;
    const float* arp;
    if (MODE==GM_MG || MODE==GM_MU)
        arp = aval ? (A + (size_t)g_list[z * Tc + agl] * lda) : A;
    else
        arp = A + (size_t)agl * lda;
    const float* bbase = Bp + n0;

    const int Kend = (MODE==GM_PV) ? (m0 + 128) : Kv;

    for (int k0 = 0; k0 < Kend; k0 += 16) {
        float4 av0 = make_float4(0.f,0.f,0.f,0.f), av1 = av0;
        if (aval) {
            av0 = *(const float4*)(arp + k0 + lk);
            av1 = *(const float4*)(arp + k0 + lk + 4);
        }
        const float4 bv0 = *(const float4*)(bbase + (size_t)(k0 + bkr) * ldb + bnc);
        const float4 bv1 = *(const float4*)(bbase + (size_t)(k0 + bkr) * ldb + bnc + 64);

        As[lk + 0][lm] = f2tf(av0.x); As[lk + 1][lm] = f2tf(av0.y);
        As[lk + 2][lm] = f2tf(av0.z); As[lk + 3][lm] = f2tf(av0.w);
        As[lk + 4][lm] = f2tf(av1.x); As[lk + 5][lm] = f2tf(av1.y);
        As[lk + 6][lm] = f2tf(av1.z); As[lk + 7][lm] = f2tf(av1.w);
        uint4 bu0, bu1;
        bu0.x = f2tf(bv0.x); bu0.y = f2tf(bv0.y); bu0.z = f2tf(bv0.z); bu0.w = f2tf(bv0.w);
        bu1.x = f2tf(bv1.x); bu1.y = f2tf(bv1.y); bu1.z = f2tf(bv1.z); bu1.w = f2tf(bv1.w);
        *(uint4*)(&Bs[bkr][bnc])      = bu0;
        *(uint4*)(&Bs[bkr][bnc + 64]) = bu1;
        __syncthreads();

#pragma unroll
        for (int ks = 0; ks < 2; ks++) {
            const int kk = ks * 8 + (lane & 3);
            const int rb = wm + (lane >> 2);
            const int cb = wn + (lane >> 2);
            uint32_t af[4][4], bf[4][2];
#pragma unroll
            for (int i = 0; i < 4; i++) {
                af[i][0] = As[kk][rb + i * 16];
                af[i][1] = As[kk][rb + i * 16 + 8];
                af[i][2] = As[kk + 4][rb + i * 16];
                af[i][3] = As[kk + 4][rb + i * 16 + 8];
            }
#pragma unroll
            for (int j = 0; j < 4; j++) {
                bf[j][0] = Bs[kk][cb + j * 8];
                bf[j][1] = Bs[kk + 4][cb + j * 8];
            }
#pragma unroll
            for (int i = 0; i < 4; i++)
#pragma unroll
                for (int j = 0; j < 4; j++)
                    mma_tf32(acc[i][j], af[i], bf[j]);
        }
        __syncthreads();
    }

    // ---------------- epilogues ----------------
    const float scl = 0.08838834764831845f;  // 1/sqrt(128)
#pragma unroll
    for (int i = 0; i < 4; i++) {
#pragma unroll
        for (int rr = 0; rr < 2; rr++) {
            const int r = m0 + wm + i * 16 + (lane >> 2) + rr * 8;
            if (r >= Mz) continue;
            if (MODE==GM_SCORES) {
                const size_t base = (size_t)z * Sc * Sc + (size_t)r * Sc;
#pragma unroll
                for (int j = 0; j < 4; j++) {
                    const int c = n0 + wn + j * 8 + (lane & 3) * 2;
                    float v0 = acc[i][j][rr * 2 + 0] * scl;
                    float v1 = acc[i][j][rr * 2 + 1] * scl;
                    if (c > r)     v0 = -1e9f;
                    if (c + 1 > r) v1 = -1e9f;
                    g_sc[base + c]     = v0;
                    g_sc[base + c + 1] = v1;
                }
            } else if (MODE==GM_MD) {
                const int tok = g_list[z * Tc + r];
                const float w = g_dw[tok * Ec + z];
                float* dst = g_moe + (size_t)tok * 2048;
#pragma unroll
                for (int j = 0; j < 4; j++) {
                    const int c = n0 + wn + j * 8 + (lane & 3) * 2;
                    atomicAdd(dst + c,     acc[i][j][rr * 2 + 0] * w);
                    atomicAdd(dst + c + 1, acc[i][j][rr * 2 + 1] * w);
                }
            } else {
                float* Cp; int ldc; const float* bias = nullptr; const float* res = nullptr;
                if (MODE==GM_Q)       { Cp = g_q;  ldc = 2048; bias = extra; }
                else if (MODE==GM_K)  { Cp = g_k;  ldc = 256;  bias = extra; }
                else if (MODE==GM_V)  { Cp = g_v;  ldc = 256;  bias = extra; }
                else if (MODE==GM_PV) { Cp = g_ao + (size_t)bb * Sc * 2048 + hh * 128; ldc = 2048; }
                else if (MODE==GM_O)  { Cp = g_x;  ldc = 2048; res = extra; }
                else if (MODE==GM_MG) { Cp = g_mg + (size_t)z * Tc * IM; ldc = IM; }
                else if (MODE==GM_MU) { Cp = g_mu + (size_t)z * Tc * IM; ldc = IM; }
                else if (MODE==GM_SG) { Cp = g_sgv; ldc = ISH; }
                else if (MODE==GM_SU) { Cp = g_suv; ldc = ISH; }
                else                  { Cp = g_sh;  ldc = 2048; }
                const size_t rowoff = (size_t)r * ldc;
#pragma unroll
                for (int j = 0; j < 4; j++) {
                    const int c = n0 + wn + j * 8 + (lane & 3) * 2;
                    float v0 = acc[i][j][rr * 2 + 0];
                    float v1 = acc[i][j][rr * 2 + 1];
                    if (bias) { v0 += bias[c]; v1 += bias[c + 1]; }
                    if (res)  { v0 += res[rowoff + c]; v1 += res[rowoff + c + 1]; }
                    Cp[rowoff + c]     = v0;
                    Cp[rowoff + c + 1] = v1;
                }
            }
        }
    }
}

// ---------------- launch ----------------
extern "C" void kernel_launch(void* const* d_in, const int* in_sizes, int n_in,
                              void* d_out, int out_size) {
    (void)in_sizes; (void)n_in; (void)out_size;
    const float* x0  = (const float*)d_in[0];
    const float* ln1 = (const float*)d_in[1];
    const float* wq  = (const float*)d_in[2];
    const float* bq  = (const float*)d_in[3];
    const float* wk  = (const float*)d_in[4];
    const float* bk  = (const float*)d_in[5];
    const float* wv  = (const float*)d_in[6];
    const float* bv  = (const float*)d_in[7];
    const float* wo  = (const float*)d_in[8];
    const float* ln2 = (const float*)d_in[9];
    const float* rw  = (const float*)d_in[10];
    const float* wg  = (const float*)d_in[11];
    const float* wu  = (const float*)d_in[12];
    const float* wd  = (const float*)d_in[13];
    const float* swg = (const float*)d_in[14];
    const float* swu = (const float*)d_in[15];
    const float* swd = (const float*)d_in[16];
    const float* sgw = (const float*)d_in[17];
    float* out = (float*)d_out;

    clear_cnt_kernel<<<1, 32>>>();
    clear_moe_kernel<<<(Tc * Hc) / 256, 256>>>();

    // attention
    rmsnorm_kernel<0><<<Tc, 256>>>(x0, ln1);
    gemm_kernel<GM_Q><<<dim3(16, 32, 1), 256>>>(wq, bq);
    gemm_kernel<GM_K><<<dim3(2, 32, 1), 256>>>(wk, bk);
    gemm_kernel<GM_V><<<dim3(2, 32, 1), 256>>>(wv, bv);
    rope_kernel<<<dim3(Tc, NQc + NKVc), 64>>>();
    kT_kernel<<<(Bc * NKVc * DHc * Sc) / 256, 256>>>();
    gemm_kernel<GM_SCORES><<<dim3(16, 16, 32), 256>>>(nullptr, nullptr);
    softmax_kernel<<<Bc * NQc * Sc, 256>>>();
    gemm_kernel<GM_PV><<<dim3(1, 16, 32), 256>>>(nullptr, nullptr);
    gemm_kernel<GM_O><<<dim3(16, 32, 1), 256>>>(wo, x0);

    // MoE block
    rmsnorm_kernel<1><<<Tc, 256>>>(nullptr, ln2);
    router_kernel<<<Tc / 8, 256>>>(rw);
    gemm_kernel<GM_MG><<<dim3(11, 32, 8), 256>>>(wg, nullptr);
    gemm_kernel<GM_MU><<<dim3(11, 32, 8), 256>>>(wu, nullptr);
    moe_act_kernel<<<dim3(6, Tc, 8), 256>>>();
    gemm_kernel<GM_MD><<<dim3(16, 32, 8), 256>>>(wd, nullptr);

    // shared expert
    gemm_kernel<GM_SG><<<dim3(44, 32, 1), 256>>>(swg, nullptr);
    gemm_kernel<GM_SU><<<dim3(44, 32, 1), 256>>>(swu, nullptr);
    shared_act_kernel<<<(size_t)(Tc) * ISH / 256, 256>>>();
    sgate_kernel<<<Tc / 8, 256>>>(sgw);
    gemm_kernel<GM_SD><<<dim3(16, 32, 1), 256>>>(swd, nullptr);

    final_kernel<<<(Tc * Hc) / 256, 256>>>(out);
}

// round 3
// speedup vs baseline: 2.7802x; 1.0605x over previous
#include <cuda_runtime.h>
#include <math.h>
#include <stdint.h>

// ---------------- problem constants ----------------
constexpr int Bc   = 2;
constexpr int Sc   = 2048;
constexpr int Hc   = 2048;
constexpr int Tc   = Bc * Sc;      // 4096 tokens
constexpr int Ec   = 8;
constexpr int IM   = 1408;
constexpr int ISH  = 5632;
constexpr int NQc  = 16;
constexpr int NKVc = 2;
constexpr int DHc  = 128;
constexpr float EPSc = 1e-5f;

// ---------------- scratch (device globals; no allocations allowed) ----------------
__device__ float g_h  [(size_t)Tc * Hc];
__device__ float g_q  [(size_t)Tc * NQc * DHc];
__device__ float g_k  [(size_t)Tc * NKVc * DHc];
__device__ float g_v  [(size_t)Tc * NKVc * DHc];
__device__ float g_kT [(size_t)Bc * NKVc * DHc * Sc];
__device__ float g_sc [(size_t)Bc * NQc * Sc * Sc];   // scores -> probs in place
__device__ float g_ao [(size_t)Tc * Hc];
__device__ float g_x  [(size_t)Tc * Hc];
__device__ float g_t2 [(size_t)Tc * Hc];
__device__ float g_dw [Tc * Ec];
__device__ int   g_cnt[Ec];
__device__ int   g_list[Ec * Tc];
__device__ float g_mg [(size_t)Ec * Tc * IM];
__device__ float g_mu [(size_t)Ec * Tc * IM];
__device__ float g_moe[(size_t)Tc * Hc];
__device__ float g_sgv[(size_t)Tc * ISH];
__device__ float g_suv[(size_t)Tc * ISH];
__device__ float g_sh [(size_t)Tc * Hc];
__device__ float g_sgate[Tc];

// ---------------- small kernels ----------------
__global__ void clear_cnt_kernel() {
    if (threadIdx.x < Ec) g_cnt[threadIdx.x] = 0;
}
__global__ void clear_moe_kernel() {
    g_moe[(size_t)blockIdx.x * 256 + threadIdx.x] = 0.f;
}

template<int PHASE>
__global__ void rmsnorm_kernel(const float* __restrict__ xin,
                               const float* __restrict__ scale) {
    __shared__ float red[256];
    const int row = blockIdx.x;
    const float* x = (PHASE == 0) ? (xin + (size_t)row * Hc) : (g_x + (size_t)row * Hc);
    float* out = (PHASE == 0) ? (g_h + (size_t)row * Hc) : (g_t2 + (size_t)row * Hc);
    float s = 0.f;
    for (int i = threadIdx.x; i < Hc; i += 256) { float v = x[i]; s += v * v; }
    red[threadIdx.x] = s; __syncthreads();
    for (int o = 128; o > 0; o >>= 1) {
        if (threadIdx.x < o) red[threadIdx.x] += red[threadIdx.x + o];
        __syncthreads();
    }
    const float inv = rsqrtf(red[0] / (float)Hc + EPSc);
    for (int i = threadIdx.x; i < Hc; i += 256) out[i] = x[i] * inv * scale[i];
}

__global__ void rope_kernel() {
    const int tok  = blockIdx.x;
    const int head = blockIdx.y;
    const int j    = threadIdx.x;         // 0..63
    const int s    = tok & (Sc - 1);
    const float inv = powf(10000.f, -(float)(2 * j) / 128.f);
    const float ang = (float)s * inv;
    float si, c;
    sincosf(ang, &si, &c);
    float* p = (head < NQc) ? (g_q + (size_t)tok * (NQc * DHc) + head * DHc)
                            : (g_k + (size_t)tok * (NKVc * DHc) + (head - NQc) * DHc);
    const float x1 = p[j], x2 = p[j + 64];
    p[j]      = x1 * c - x2 * si;
    p[j + 64] = x2 * c + x1 * si;
}

__global__ void kT_kernel() {
    const int i  = blockIdx.x * 256 + threadIdx.x;
    const int s  = i & (Sc - 1);
    const int d  = (i >> 11) & 127;
    const int bk = i >> 18;
    g_kT[i] = g_k[((size_t)((bk >> 1) * Sc + s)) * (NKVc * DHc) + (bk & 1) * DHc + d];
}

__global__ void softmax_kernel() {
    __shared__ float red[256];
    const size_t rid = blockIdx.x;
    const int r   = (int)(rid & (Sc - 1));
    float* sc = g_sc + rid * Sc;
    const int lim = r + 1;
    const int tid = threadIdx.x;
    float m = -1e30f;
    for (int c = tid; c < lim; c += 256) m = fmaxf(m, sc[c]);
    red[tid] = m; __syncthreads();
    for (int o = 128; o > 0; o >>= 1) {
        if (tid < o) red[tid] = fmaxf(red[tid], red[tid + o]);
        __syncthreads();
    }
    m = red[0]; __syncthreads();
    float s = 0.f;
    for (int c = tid; c < lim; c += 256) s += expf(sc[c] - m);
    red[tid] = s; __syncthreads();
    for (int o = 128; o > 0; o >>= 1) {
        if (tid < o) red[tid] += red[tid + o];
        __syncthreads();
    }
    const float inv = 1.f / red[0];
    for (int c = tid; c < Sc; c += 256)
        sc[c] = (c < lim) ? expf(sc[c] - m) * inv : 0.f;
}

__global__ void router_kernel(const float* __restrict__ rw) {
    const int tok  = blockIdx.x * 8 + (threadIdx.x >> 5);
    const int lane = threadIdx.x & 31;
    const float* tr = g_t2 + (size_t)tok * Hc;
    float acc[8];
#pragma unroll
    for (int e = 0; e < 8; e++) acc[e] = 0.f;
    for (int h = lane; h < Hc; h += 32) {
        const float tv = tr[h];
        const float* rp = rw + h * 8;
#pragma unroll
        for (int e = 0; e < 8; e++) acc[e] += tv * rp[e];
    }
#pragma unroll
    for (int e = 0; e < 8; e++)
        for (int o = 16; o; o >>= 1) acc[e] += __shfl_xor_sync(0xffffffffu, acc[e], o);
    if (lane == 0) {
        float m = acc[0];
        for (int e = 1; e < 8; e++) m = fmaxf(m, acc[e]);
        float p[8], s = 0.f;
        for (int e = 0; e < 8; e++) { p[e] = expf(acc[e] - m); s += p[e]; }
        for (int e = 0; e < 8; e++) p[e] /= s;
        bool used[8] = {false,false,false,false,false,false,false,false};
        int isel[4]; float wsel[4]; float tsum = 0.f;
        for (int kk = 0; kk < 4; kk++) {
            int best = 0; float bv = -1.f;
            for (int e = 0; e < 8; e++)
                if (!used[e] && p[e] > bv) { bv = p[e]; best = e; }
            used[best] = true; isel[kk] = best; wsel[kk] = bv; tsum += bv;
        }
        float outw[8] = {0,0,0,0,0,0,0,0};
        for (int kk = 0; kk < 4; kk++) outw[isel[kk]] = wsel[kk] / tsum;
        for (int e = 0; e < 8; e++) g_dw[tok * 8 + e] = outw[e];
        for (int kk = 0; kk < 4; kk++) {
            const int pos = atomicAdd(&g_cnt[isel[kk]], 1);
            g_list[isel[kk] * Tc + pos] = tok;
        }
    }
}

__global__ void moe_act_kernel() {
    const int e = blockIdx.z, row = blockIdx.y;
    if (row >= g_cnt[e]) return;
    const int col = blockIdx.x * 256 + threadIdx.x;
    if (col >= IM) return;
    const size_t i = ((size_t)e * Tc + row) * IM + col;
    const float g = g_mg[i], u = g_mu[i];
    g_mg[i] = g / (1.f + expf(-g)) * u;
}

__global__ void shared_act_kernel() {
    const size_t i = (size_t)blockIdx.x * 256 + threadIdx.x;
    const float g = g_sgv[i], u = g_suv[i];
    g_sgv[i] = g / (1.f + expf(-g)) * u;
}

__global__ void sgate_kernel(const float* __restrict__ sgw) {
    const int tok  = blockIdx.x * 8 + (threadIdx.x >> 5);
    const int lane = threadIdx.x & 31;
    const float* tr = g_t2 + (size_t)tok * Hc;
    float s = 0.f;
    for (int h = lane; h < Hc; h += 32) s += tr[h] * sgw[h];
    for (int o = 16; o; o >>= 1) s += __shfl_xor_sync(0xffffffffu, s, o);
    if (lane == 0) g_sgate[tok] = 1.f / (1.f + expf(-s));
}

__global__ void final_kernel(float* __restrict__ out) {
    const size_t i = (size_t)blockIdx.x * 256 + threadIdx.x;
    const int row = (int)(i >> 11);
    out[i] = g_x[i] + g_moe[i] + g_sgate[row] * g_sh[i];
}

// ---------------- tf32 tensor-core universal GEMM (double-buffered) ----------------
enum GMode { GM_Q, GM_K, GM_V, GM_SCORES, GM_PV, GM_O,
             GM_MG, GM_MU, GM_MD, GM_SG, GM_SU, GM_SD };

__device__ __forceinline__ uint32_t f2tf(float x) {
    uint32_t r;
    asm("cvt.rna.tf32.f32 %0, %1;" : "=r"(r) : "f"(x));
    return r;
}

__device__ __forceinline__ void mma_tf32(float* c, const uint32_t* a, const uint32_t* b) {
    asm volatile(
        "mma.sync.aligned.m16n8k8.row.col.f32.tf32.tf32.f32 "
        "{%0,%1,%2,%3}, {%4,%5,%6,%7}, {%8,%9}, {%0,%1,%2,%3};"
        : "+f"(c[0]), "+f"(c[1]), "+f"(c[2]), "+f"(c[3])
        : "r"(a[0]), "r"(a[1]), "r"(a[2]), "r"(a[3]), "r"(b[0]), "r"(b[1]));
}

// BM=128, BN=128, BK=16; 256 threads = 8 warps (2 x 4), warp tile 64x32.
// Double-buffered smem, one sync per K-tile, 2 CTAs/SM.
template<int MODE>
__global__ __launch_bounds__(256, 2) void gemm_kernel(const float* __restrict__ W,
                                                      const float* __restrict__ extra) {
    constexpr int Kv =
        (MODE==GM_SCORES) ? 128 :
        (MODE==GM_PV) ? Sc :
        (MODE==GM_MD) ? IM :
        (MODE==GM_SD) ? ISH : 2048;

    const int tid = threadIdx.x;
    const int z   = blockIdx.z;
    const int m0  = blockIdx.y * 128, n0 = blockIdx.x * 128;

    int Mz;
    if (MODE==GM_SCORES || MODE==GM_PV) Mz = Sc;
    else if (MODE==GM_MG || MODE==GM_MU || MODE==GM_MD) Mz = g_cnt[z];
    else Mz = Tc;
    if (m0 >= Mz) return;
    if (MODE==GM_SCORES && n0 > m0 + 127) return;   // fully masked tile

    int bb = 0, hh = 0;
    if (MODE==GM_SCORES || MODE==GM_PV) { bb = z >> 4; hh = z & 15; }

    const float* A; const float* Bp; int lda, ldb;
    if (MODE==GM_Q || MODE==GM_K || MODE==GM_V) {
        A = g_h; lda = Hc; Bp = W; ldb = (MODE==GM_Q) ? 2048 : 256;
    } else if (MODE==GM_SCORES) {
        A = g_q + (size_t)bb * Sc * 2048 + hh * 128; lda = 2048;
        Bp = g_kT + (size_t)(bb * 2 + (hh >> 3)) * 128 * Sc; ldb = Sc;
    } else if (MODE==GM_PV) {
        A = g_sc + (size_t)z * Sc * Sc; lda = Sc;
        Bp = g_v + (size_t)bb * Sc * 256 + (hh >> 3) * 128; ldb = 256;
    } else if (MODE==GM_O) {
        A = g_ao; lda = 2048; Bp = W; ldb = 2048;
    } else if (MODE==GM_MG || MODE==GM_MU) {
        A = g_t2; lda = 2048; Bp = W + (size_t)z * 2048 * IM; ldb = IM;
    } else if (MODE==GM_MD) {
        A = g_mg + (size_t)z * Tc * IM; lda = IM;
        Bp = W + (size_t)z * IM * 2048; ldb = 2048;
    } else if (MODE==GM_SG || MODE==GM_SU) {
        A = g_t2; lda = 2048; Bp = W; ldb = ISH;
    } else { // GM_SD
        A = g_sgv; lda = ISH; Bp = W; ldb = 2048;
    }

    // smem: A transposed [k][m], B [k][n]; stride 136 -> conflict-free fragment LDS
    __shared__ uint32_t As[2][16][136];
    __shared__ uint32_t Bs[2][16][136];

    float acc[4][4][4];
#pragma unroll
    for (int i = 0; i < 4; i++)
#pragma unroll
        for (int j = 0; j < 4; j++)
#pragma unroll
            for (int r = 0; r < 4; r++) acc[i][j][r] = 0.f;

    const int lane = tid & 31, wid = tid >> 5;
    const int wm = (wid >> 2) * 64;     // warp row offset (0 / 64)
    const int wn = (wid & 3) * 32;      // warp col offset (0/32/64/96)

    // loader indices
    const int lm = tid >> 1, lk = (tid & 1) * 8;        // A: row lm, k chunk lk
    const int bkr = tid >> 4, bnc = (tid & 15) * 4;     // B: row bkr, col chunk bnc

    const int agl  = m0 + lm;
    const bool aval = agl < Mz;
    const float* arp;
    if (MODE==GM_MG || MODE==GM_MU)
        arp = aval ? (A + (size_t)g_list[z * Tc + agl] * lda) : A;
    else
        arp = A + (size_t)agl * lda;
    const float* bbase = Bp + n0;

    const int Kend = (MODE==GM_PV) ? (m0 + 128) : Kv;
    const int nt = Kend / 16;

    float4 av0, av1, bv0, bv1;

    // prologue: load tile 0
    av0 = make_float4(0.f,0.f,0.f,0.f); av1 = av0;
    if (aval) {
        av0 = *(const float4*)(arp + lk);
        av1 = *(const float4*)(arp + lk + 4);
    }
    bv0 = *(const float4*)(bbase + (size_t)bkr * ldb + bnc);
    bv1 = *(const float4*)(bbase + (size_t)bkr * ldb + bnc + 64);
    {
        uint32_t* a = &As[0][lk][lm];
        a[0*136] = f2tf(av0.x); a[1*136] = f2tf(av0.y);
        a[2*136] = f2tf(av0.z); a[3*136] = f2tf(av0.w);
        a[4*136] = f2tf(av1.x); a[5*136] = f2tf(av1.y);
        a[6*136] = f2tf(av1.z); a[7*136] = f2tf(av1.w);
        uint4 u0, u1;
        u0.x = f2tf(bv0.x); u0.y = f2tf(bv0.y); u0.z = f2tf(bv0.z); u0.w = f2tf(bv0.w);
        u1.x = f2tf(bv1.x); u1.y = f2tf(bv1.y); u1.z = f2tf(bv1.z); u1.w = f2tf(bv1.w);
        *(uint4*)(&Bs[0][bkr][bnc])      = u0;
        *(uint4*)(&Bs[0][bkr][bnc + 64]) = u1;
    }
    __syncthreads();

    const int rb = wm + (lane >> 2);
    const int cb = wn + (lane >> 2);
    const int kq = lane & 3;

    for (int t = 0; t < nt; t++) {
        const int buf = t & 1;
        const bool more = (t + 1) < nt;
        if (more) {
            const int k0 = (t + 1) * 16;
            av0 = make_float4(0.f,0.f,0.f,0.f); av1 = av0;
            if (aval) {
                av0 = *(const float4*)(arp + k0 + lk);
                av1 = *(const float4*)(arp + k0 + lk + 4);
            }
            bv0 = *(const float4*)(bbase + (size_t)(k0 + bkr) * ldb + bnc);
            bv1 = *(const float4*)(bbase + (size_t)(k0 + bkr) * ldb + bnc + 64);
        }

#pragma unroll
        for (int ks = 0; ks < 2; ks++) {
            const int kk = ks * 8 + kq;
            uint32_t af[4][4], bf[4][2];
#pragma unroll
            for (int i = 0; i < 4; i++) {
                af[i][0] = As[buf][kk][rb + i * 16];
                af[i][1] = As[buf][kk][rb + i * 16 + 8];
                af[i][2] = As[buf][kk + 4][rb + i * 16];
                af[i][3] = As[buf][kk + 4][rb + i * 16 + 8];
            }
#pragma unroll
            for (int j = 0; j < 4; j++) {
                bf[j][0] = Bs[buf][kk][cb + j * 8];
                bf[j][1] = Bs[buf][kk + 4][cb + j * 8];
            }
#pragma unroll
            for (int i = 0; i < 4; i++)
#pragma unroll
                for (int j = 0; j < 4; j++)
                    mma_tf32(acc[i][j], af[i], bf[j]);
        }

        if (more) {
            uint32_t* a = &As[buf ^ 1][lk][lm];
            a[0*136] = f2tf(av0.x); a[1*136] = f2tf(av0.y);
            a[2*136] = f2tf(av0.z); a[3*136] = f2tf(av0.w);
            a[4*136] = f2tf(av1.x); a[5*136] = f2tf(av1.y);
            a[6*136] = f2tf(av1.z); a[7*136] = f2tf(av1.w);
            uint4 u0, u1;
            u0.x = f2tf(bv0.x); u0.y = f2tf(bv0.y); u0.z = f2tf(bv0.z); u0.w = f2tf(bv0.w);
            u1.x = f2tf(bv1.x); u1.y = f2tf(bv1.y); u1.z = f2tf(bv1.z); u1.w = f2tf(bv1.w);
            *(uint4*)(&Bs[buf ^ 1][bkr][bnc])      = u0;
            *(uint4*)(&Bs[buf ^ 1][bkr][bnc + 64]) = u1;
            __syncthreads();
        }
    }

    // ---------------- epilogues ----------------
    const float scl = 0.08838834764831845f;  // 1/sqrt(128)
#pragma unroll
    for (int i = 0; i < 4; i++) {
#pragma unroll
        for (int rr = 0; rr < 2; rr++) {
            const int r = m0 + wm + i * 16 + (lane >> 2) + rr * 8;
            if (r >= Mz) continue;
            if (MODE==GM_SCORES) {
                const size_t base = (size_t)z * Sc * Sc + (size_t)r * Sc;
#pragma unroll
                for (int j = 0; j < 4; j++) {
                    const int c = n0 + wn + j * 8 + (lane & 3) * 2;
                    float v0 = acc[i][j][rr * 2 + 0] * scl;
                    float v1 = acc[i][j][rr * 2 + 1] * scl;
                    if (c > r)     v0 = -1e9f;
                    if (c + 1 > r) v1 = -1e9f;
                    g_sc[base + c]     = v0;
                    g_sc[base + c + 1] = v1;
                }
            } else if (MODE==GM_MD) {
                const int tok = g_list[z * Tc + r];
                const float w = g_dw[tok * Ec + z];
                float* dst = g_moe + (size_t)tok * 2048;
#pragma unroll
                for (int j = 0; j < 4; j++) {
                    const int c = n0 + wn + j * 8 + (lane & 3) * 2;
                    atomicAdd(dst + c,     acc[i][j][rr * 2 + 0] * w);
                    atomicAdd(dst + c + 1, acc[i][j][rr * 2 + 1] * w);
                }
            } else {
                float* Cp; int ldc; const float* bias = nullptr; const float* res = nullptr;
                if (MODE==GM_Q)       { Cp = g_q;  ldc = 2048; bias = extra; }
                else if (MODE==GM_K)  { Cp = g_k;  ldc = 256;  bias = extra; }
                else if (MODE==GM_V)  { Cp = g_v;  ldc = 256;  bias = extra; }
                else if (MODE==GM_PV) { Cp = g_ao + (size_t)bb * Sc * 2048 + hh * 128; ldc = 2048; }
                else if (MODE==GM_O)  { Cp = g_x;  ldc = 2048; res = extra; }
                else if (MODE==GM_MG) { Cp = g_mg + (size_t)z * Tc * IM; ldc = IM; }
                else if (MODE==GM_MU) { Cp = g_mu + (size_t)z * Tc * IM; ldc = IM; }
                else if (MODE==GM_SG) { Cp = g_sgv; ldc = ISH; }
                else if (MODE==GM_SU) { Cp = g_suv; ldc = ISH; }
                else                  { Cp = g_sh;  ldc = 2048; }
                const size_t rowoff = (size_t)r * ldc;
#pragma unroll
                for (int j = 0; j < 4; j++) {
                    const int c = n0 + wn + j * 8 + (lane & 3) * 2;
                    float v0 = acc[i][j][rr * 2 + 0];
                    float v1 = acc[i][j][rr * 2 + 1];
                    if (bias) { v0 += bias[c]; v1 += bias[c + 1]; }
                    if (res)  { v0 += res[rowoff + c]; v1 += res[rowoff + c + 1]; }
                    Cp[rowoff + c]     = v0;
                    Cp[rowoff + c + 1] = v1;
                }
            }
        }
    }
}

// ---------------- launch ----------------
extern "C" void kernel_launch(void* const* d_in, const int* in_sizes, int n_in,
                              void* d_out, int out_size) {
    (void)in_sizes; (void)n_in; (void)out_size;
    const float* x0  = (const float*)d_in[0];
    const float* ln1 = (const float*)d_in[1];
    const float* wq  = (const float*)d_in[2];
    const float* bq  = (const float*)d_in[3];
    const float* wk  = (const float*)d_in[4];
    const float* bk  = (const float*)d_in[5];
    const float* wv  = (const float*)d_in[6];
    const float* bv  = (const float*)d_in[7];
    const float* wo  = (const float*)d_in[8];
    const float* ln2 = (const float*)d_in[9];
    const float* rw  = (const float*)d_in[10];
    const float* wg  = (const float*)d_in[11];
    const float* wu  = (const float*)d_in[12];
    const float* wd  = (const float*)d_in[13];
    const float* swg = (const float*)d_in[14];
    const float* swu = (const float*)d_in[15];
    const float* swd = (const float*)d_in[16];
    const float* sgw = (const float*)d_in[17];
    float* out = (float*)d_out;

    clear_cnt_kernel<<<1, 32>>>();
    clear_moe_kernel<<<(Tc * Hc) / 256, 256>>>();

    // attention
    rmsnorm_kernel<0><<<Tc, 256>>>(x0, ln1);
    gemm_kernel<GM_Q><<<dim3(16, 32, 1), 256>>>(wq, bq);
    gemm_kernel<GM_K><<<dim3(2, 32, 1), 256>>>(wk, bk);
    gemm_kernel<GM_V><<<dim3(2, 32, 1), 256>>>(wv, bv);
    rope_kernel<<<dim3(Tc, NQc + NKVc), 64>>>();
    kT_kernel<<<(Bc * NKVc * DHc * Sc) / 256, 256>>>();
    gemm_kernel<GM_SCORES><<<dim3(16, 16, 32), 256>>>(nullptr, nullptr);
    softmax_kernel<<<Bc * NQc * Sc, 256>>>();
    gemm_kernel<GM_PV><<<dim3(1, 16, 32), 256>>>(nullptr, nullptr);
    gemm_kernel<GM_O><<<dim3(16, 32, 1), 256>>>(wo, x0);

    // MoE block
    rmsnorm_kernel<1><<<Tc, 256>>>(nullptr, ln2);
    router_kernel<<<Tc / 8, 256>>>(rw);
    gemm_kernel<GM_MG><<<dim3(11, 32, 8), 256>>>(wg, nullptr);
    gemm_kernel<GM_MU><<<dim3(11, 32, 8), 256>>>(wu, nullptr);
    moe_act_kernel<<<dim3(6, Tc, 8), 256>>>();
    gemm_kernel<GM_MD><<<dim3(16, 32, 8), 256>>>(wd, nullptr);

    // shared expert
    gemm_kernel<GM_SG><<<dim3(44, 32, 1), 256>>>(swg, nullptr);
    gemm_kernel<GM_SU><<<dim3(44, 32, 1), 256>>>(swu, nullptr);
    shared_act_kernel<<<(size_t)(Tc) * ISH / 256, 256>>>();
    sgate_kernel<<<Tc / 8, 256>>>(sgw);
    gemm_kernel<GM_SD><<<dim3(16, 32, 1), 256>>>(swd, nullptr);

    final_kernel<<<(Tc * Hc) / 256, 256>>>(out);
}

// round 5
// speedup vs baseline: 2.9181x; 1.0496x over previous
#include <cuda_runtime.h>
#include <math.h>
#include <stdint.h>

// ---------------- problem constants ----------------
constexpr int Bc   = 2;
constexpr int Sc   = 2048;
constexpr int Hc   = 2048;
constexpr int Tc   = Bc * Sc;      // 4096 tokens
constexpr int Ec   = 8;
constexpr int IM   = 1408;
constexpr int ISH  = 5632;
constexpr int NQc  = 16;
constexpr int NKVc = 2;
constexpr int DHc  = 128;
constexpr float EPSc = 1e-5f;

// rounded-weight scratch offsets
constexpr size_t OFF_WQ  = 0;
constexpr size_t OFF_WK  = OFF_WQ  + (size_t)2048 * 2048;
constexpr size_t OFF_WV  = OFF_WK  + (size_t)2048 * 256;
constexpr size_t OFF_WO  = OFF_WV  + (size_t)2048 * 256;
constexpr size_t OFF_WG  = OFF_WO  + (size_t)2048 * 2048;
constexpr size_t OFF_WU  = OFF_WG  + (size_t)Ec * 2048 * IM;
constexpr size_t OFF_WD  = OFF_WU  + (size_t)Ec * 2048 * IM;
constexpr size_t OFF_SWG = OFF_WD  + (size_t)Ec * IM * 2048;
constexpr size_t OFF_SWU = OFF_SWG + (size_t)2048 * ISH;
constexpr size_t OFF_SWD = OFF_SWU + (size_t)2048 * ISH;
constexpr size_t WR_TOT  = OFF_SWD + (size_t)ISH * 2048;

// ---------------- scratch (device globals; no allocations allowed) ----------------
__device__ float g_wr [WR_TOT];                      // tf32-rounded weights
__device__ float g_h  [(size_t)Tc * Hc];
__device__ float g_q  [(size_t)Tc * NQc * DHc];
__device__ float g_k  [(size_t)Tc * NKVc * DHc];
__device__ float g_v  [(size_t)Tc * NKVc * DHc];
__device__ float g_kT [(size_t)Bc * NKVc * DHc * Sc];
__device__ float g_sc [(size_t)Bc * NQc * Sc * Sc];  // scores -> probs in place
__device__ float g_ao [(size_t)Tc * Hc];
__device__ float g_x  [(size_t)Tc * Hc];
__device__ float g_t2 [(size_t)Tc * Hc];             // exact (router/sgate)
__device__ float g_t2r[(size_t)Tc * Hc];             // tf32-rounded (GEMM A)
__device__ float g_dw [Tc * Ec];
__device__ int   g_cnt[Ec];
__device__ int   g_list[Ec * Tc];
__device__ float g_mg [(size_t)Ec * Tc * IM];
__device__ float g_mu [(size_t)Ec * Tc * IM];
__device__ float g_moe[(size_t)Tc * Hc];
__device__ float g_sgv[(size_t)Tc * ISH];
__device__ float g_suv[(size_t)Tc * ISH];
__device__ float g_sh [(size_t)Tc * Hc];
__device__ float g_sgate[Tc];

__device__ __forceinline__ float tf32r(float x) {
    uint32_t u;
    asm("cvt.rna.tf32.f32 %0, %1;" : "=r"(u) : "f"(x));
    return __uint_as_float(u);
}

// ---------------- weight rounding ----------------
template<size_t OFF>
__global__ void round_copy_kernel(const float* __restrict__ src, int n) {
    const int i = blockIdx.x * 256 + threadIdx.x;
    if (i < n) g_wr[OFF + i] = tf32r(src[i]);
}

// ---------------- small kernels ----------------
__global__ void clear_cnt_kernel() {
    if (threadIdx.x < Ec) g_cnt[threadIdx.x] = 0;
}
__global__ void clear_moe_kernel() {
    g_moe[(size_t)blockIdx.x * 256 + threadIdx.x] = 0.f;
}

template<int PHASE>
__global__ void rmsnorm_kernel(const float* __restrict__ xin,
                               const float* __restrict__ scale) {
    __shared__ float red[256];
    const int row = blockIdx.x;
    const float* x = (PHASE == 0) ? (xin + (size_t)row * Hc) : (g_x + (size_t)row * Hc);
    float s = 0.f;
    for (int i = threadIdx.x; i < Hc; i += 256) { float v = x[i]; s += v * v; }
    red[threadIdx.x] = s; __syncthreads();
    for (int o = 128; o > 0; o >>= 1) {
        if (threadIdx.x < o) red[threadIdx.x] += red[threadIdx.x + o];
        __syncthreads();
    }
    const float inv = rsqrtf(red[0] / (float)Hc + EPSc);
    for (int i = threadIdx.x; i < Hc; i += 256) {
        const float v = x[i] * inv * scale[i];
        if (PHASE == 0) {
            g_h[(size_t)row * Hc + i] = tf32r(v);
        } else {
            g_t2 [(size_t)row * Hc + i] = v;
            g_t2r[(size_t)row * Hc + i] = tf32r(v);
        }
    }
}

__global__ void rope_kernel() {
    const int tok  = blockIdx.x;
    const int head = blockIdx.y;
    const int j    = threadIdx.x;         // 0..63
    const int s    = tok & (Sc - 1);
    const float inv = powf(10000.f, -(float)(2 * j) / 128.f);
    const float ang = (float)s * inv;
    float si, c;
    sincosf(ang, &si, &c);
    float* p = (head < NQc) ? (g_q + (size_t)tok * (NQc * DHc) + head * DHc)
                            : (g_k + (size_t)tok * (NKVc * DHc) + (head - NQc) * DHc);
    const float x1 = p[j], x2 = p[j + 64];
    p[j]      = tf32r(x1 * c - x2 * si);
    p[j + 64] = tf32r(x2 * c + x1 * si);
}

__global__ void kT_kernel() {
    const int i  = blockIdx.x * 256 + threadIdx.x;
    const int s  = i & (Sc - 1);
    const int d  = (i >> 11) & 127;
    const int bk = i >> 18;
    g_kT[i] = g_k[((size_t)((bk >> 1) * Sc + s)) * (NKVc * DHc) + (bk & 1) * DHc + d];
}

__global__ void softmax_kernel() {
    __shared__ float red[256];
    const size_t rid = blockIdx.x;
    const int r   = (int)(rid & (Sc - 1));
    float* sc = g_sc + rid * Sc;
    const int lim = r + 1;
    const int tid = threadIdx.x;
    float m = -1e30f;
    for (int c = tid; c < lim; c += 256) m = fmaxf(m, sc[c]);
    red[tid] = m; __syncthreads();
    for (int o = 128; o > 0; o >>= 1) {
        if (tid < o) red[tid] = fmaxf(red[tid], red[tid + o]);
        __syncthreads();
    }
    m = red[0]; __syncthreads();
    float s = 0.f;
    for (int c = tid; c < lim; c += 256) s += expf(sc[c] - m);
    red[tid] = s; __syncthreads();
    for (int o = 128; o > 0; o >>= 1) {
        if (tid < o) red[tid] += red[tid + o];
        __syncthreads();
    }
    const float inv = 1.f / red[0];
    for (int c = tid; c < Sc; c += 256)
        sc[c] = (c < lim) ? tf32r(expf(sc[c] - m) * inv) : 0.f;
}

__global__ void router_kernel(const float* __restrict__ rw) {
    const int tok  = blockIdx.x * 8 + (threadIdx.x >> 5);
    const int lane = threadIdx.x & 31;
    const float* tr = g_t2 + (size_t)tok * Hc;
    float acc[8];
#pragma unroll
    for (int e = 0; e < 8; e++) acc[e] = 0.f;
    for (int h = lane; h < Hc; h += 32) {
        const float tv = tr[h];
        const float* rp = rw + h * 8;
#pragma unroll
        for (int e = 0; e < 8; e++) acc[e] += tv * rp[e];
    }
#pragma unroll
    for (int e = 0; e < 8; e++)
        for (int o = 16; o; o >>= 1) acc[e] += __shfl_xor_sync(0xffffffffu, acc[e], o);
    if (lane == 0) {
        float m = acc[0];
        for (int e = 1; e < 8; e++) m = fmaxf(m, acc[e]);
        float p[8], s = 0.f;
        for (int e = 0; e < 8; e++) { p[e] = expf(acc[e] - m); s += p[e]; }
        for (int e = 0; e < 8; e++) p[e] /= s;
        bool used[8] = {false,false,false,false,false,false,false,false};
        int isel[4]; float wsel[4]; float tsum = 0.f;
        for (int kk = 0; kk < 4; kk++) {
            int best = 0; float bv = -1.f;
            for (int e = 0; e < 8; e++)
                if (!used[e] && p[e] > bv) { bv = p[e]; best = e; }
            used[best] = true; isel[kk] = best; wsel[kk] = bv; tsum += bv;
        }
        float outw[8] = {0,0,0,0,0,0,0,0};
        for (int kk = 0; kk < 4; kk++) outw[isel[kk]] = wsel[kk] / tsum;
        for (int e = 0; e < 8; e++) g_dw[tok * 8 + e] = outw[e];
        for (int kk = 0; kk < 4; kk++) {
            const int pos = atomicAdd(&g_cnt[isel[kk]], 1);
            g_list[isel[kk] * Tc + pos] = tok;
        }
    }
}

__global__ void moe_act_kernel() {
    const int e = blockIdx.z, row = blockIdx.y;
    if (row >= g_cnt[e]) return;
    const int col = blockIdx.x * 256 + threadIdx.x;
    if (col >= IM) return;
    const size_t i = ((size_t)e * Tc + row) * IM + col;
    const float g = g_mg[i], u = g_mu[i];
    g_mg[i] = tf32r(g / (1.f + expf(-g)) * u);
}

__global__ void shared_act_kernel() {
    const size_t i = (size_t)blockIdx.x * 256 + threadIdx.x;
    const float g = g_sgv[i], u = g_suv[i];
    g_sgv[i] = tf32r(g / (1.f + expf(-g)) * u);
}

__global__ void sgate_kernel(const float* __restrict__ sgw) {
    const int tok  = blockIdx.x * 8 + (threadIdx.x >> 5);
    const int lane = threadIdx.x & 31;
    const float* tr = g_t2 + (size_t)tok * Hc;
    float s = 0.f;
    for (int h = lane; h < Hc; h += 32) s += tr[h] * sgw[h];
    for (int o = 16; o; o >>= 1) s += __shfl_xor_sync(0xffffffffu, s, o);
    if (lane == 0) g_sgate[tok] = 1.f / (1.f + expf(-s));
}

__global__ void final_kernel(float* __restrict__ out) {
    const size_t i = (size_t)blockIdx.x * 256 + threadIdx.x;
    const int row = (int)(i >> 11);
    out[i] = g_x[i] + g_moe[i] + g_sgate[row] * g_sh[i];
}

// ---------------- tf32 tensor-core universal GEMM (cp.async, 64x64 warp tile) ----------------
enum GMode { GM_Q, GM_K, GM_V, GM_SCORES, GM_PV, GM_O,
             GM_MG, GM_MU, GM_MD, GM_SG, GM_SU, GM_SD };

__device__ __forceinline__ void mma_tf32(float* c, const uint32_t* a, const uint32_t* b) {
    asm volatile(
        "mma.sync.aligned.m16n8k8.row.col.f32.tf32.tf32.f32 "
        "{%0,%1,%2,%3}, {%4,%5,%6,%7}, {%8,%9}, {%0,%1,%2,%3};"
        : "+f"(c[0]), "+f"(c[1]), "+f"(c[2]), "+f"(c[3])
        : "r"(a[0]), "r"(a[1]), "r"(a[2]), "r"(a[3]), "r"(b[0]), "r"(b[1]));
}

__device__ __forceinline__ void cpa16(uint32_t dst, const void* src, int sz) {
    asm volatile("cp.async.cg.shared.global [%0], [%1], 16, %2;\n"
                 :: "r"(dst), "l"(src), "r"(sz));
}
__device__ __forceinline__ void cpa_commit() {
    asm volatile("cp.async.commit_group;\n");
}
__device__ __forceinline__ void cpa_wait0() {
    asm volatile("cp.async.wait_group 0;\n" ::: "memory");
}

constexpr int AST = 20;    // As stride (floats): conflict-free fragment loads
constexpr int BST = 136;   // Bs stride (floats)

// BM=128, BN=128, BK=16; 128 threads = 4 warps (2x2), warp tile 64x64.
template<int MODE>
__global__ __launch_bounds__(128, 2) void gemm_kernel(const float* __restrict__ extra) {
    constexpr int Kv =
        (MODE==GM_SCORES) ? 128 :
        (MODE==GM_PV) ? Sc :
        (MODE==GM_MD) ? IM :
        (MODE==GM_SD) ? ISH : 2048;

    const int tid = threadIdx.x;
    const int z   = blockIdx.z;
    const int m0  = blockIdx.y * 128, n0 = blockIdx.x * 128;

    int Mz;
    if (MODE==GM_SCORES || MODE==GM_PV) Mz = Sc;
    else if (MODE==GM_MG || MODE==GM_MU || MODE==GM_MD) Mz = g_cnt[z];
    else Mz = Tc;
    if (m0 >= Mz) return;
    if (MODE==GM_SCORES && n0 > m0 + 127) return;   // fully masked tile

    int bb = 0, hh = 0;
    if (MODE==GM_SCORES || MODE==GM_PV) { bb = z >> 4; hh = z & 15; }

    const float* A; const float* Bp; int lda, ldb;
    if (MODE==GM_Q) {
        A = g_h; lda = Hc; Bp = g_wr + OFF_WQ; ldb = 2048;
    } else if (MODE==GM_K) {
        A = g_h; lda = Hc; Bp = g_wr + OFF_WK; ldb = 256;
    } else if (MODE==GM_V) {
        A = g_h; lda = Hc; Bp = g_wr + OFF_WV; ldb = 256;
    } else if (MODE==GM_SCORES) {
        A = g_q + (size_t)bb * Sc * 2048 + hh * 128; lda = 2048;
        Bp = g_kT + (size_t)(bb * 2 + (hh >> 3)) * 128 * Sc; ldb = Sc;
    } else if (MODE==GM_PV) {
        A = g_sc + (size_t)z * Sc * Sc; lda = Sc;
        Bp = g_v + (size_t)bb * Sc * 256 + (hh >> 3) * 128; ldb = 256;
    } else if (MODE==GM_O) {
        A = g_ao; lda = 2048; Bp = g_wr + OFF_WO; ldb = 2048;
    } else if (MODE==GM_MG) {
        A = g_t2r; lda = 2048; Bp = g_wr + OFF_WG + (size_t)z * 2048 * IM; ldb = IM;
    } else if (MODE==GM_MU) {
        A = g_t2r; lda = 2048; Bp = g_wr + OFF_WU + (size_t)z * 2048 * IM; ldb = IM;
    } else if (MODE==GM_MD) {
        A = g_mg + (size_t)z * Tc * IM; lda = IM;
        Bp = g_wr + OFF_WD + (size_t)z * IM * 2048; ldb = 2048;
    } else if (MODE==GM_SG) {
        A = g_t2r; lda = 2048; Bp = g_wr + OFF_SWG; ldb = ISH;
    } else if (MODE==GM_SU) {
        A = g_t2r; lda = 2048; Bp = g_wr + OFF_SWU; ldb = ISH;
    } else { // GM_SD
        A = g_sgv; lda = ISH; Bp = g_wr + OFF_SWD; ldb = 2048;
    }

    __shared__ float As[2][128][AST];   // [stage][m][k]
    __shared__ float Bs[2][16][BST];    // [stage][k][n]

    float acc[4][8][4];
#pragma unroll
    for (int i = 0; i < 4; i++)
#pragma unroll
        for (int j = 0; j < 8; j++)
#pragma unroll
            for (int r = 0; r < 4; r++) acc[i][j][r] = 0.f;

    const int lane = tid & 31, wid = tid >> 5;
    const int wm = (wid >> 1) * 64;
    const int wn = (wid & 1) * 64;

    // A loader: one row per thread
    const int lm = tid;
    const int agl = m0 + lm;
    const bool aval = agl < Mz;
    const float* arp;
    if (MODE==GM_MG || MODE==GM_MU)
        arp = A + (size_t)(aval ? g_list[z * Tc + agl] : 0) * lda;
    else
        arp = A + (size_t)(aval ? agl : 0) * lda;
    const int asz = aval ? 16 : 0;
    const int arot = (lm >> 3) & 3;   // chunk rotation -> conflict-free cp.async stores

    // B loader: per warp one k-row per chunk, 128 cols split across lanes
    const int bw = tid >> 5;          // k sub-row
    const int bn = (tid & 31) * 4;
    const float* bbase = Bp + n0;

    const int Kend = (MODE==GM_PV) ? (m0 + 128) : Kv;
    const int nt = Kend / 16;

    uint32_t sA[2], sB[2];
    sA[0] = (uint32_t)__cvta_generic_to_shared(&As[0][0][0]);
    sA[1] = (uint32_t)__cvta_generic_to_shared(&As[1][0][0]);
    sB[0] = (uint32_t)__cvta_generic_to_shared(&Bs[0][0][0]);
    sB[1] = (uint32_t)__cvta_generic_to_shared(&Bs[1][0][0]);

    auto load_stage = [&](int s, int k0) {
        const float* asrc = arp + k0;
#pragma unroll
        for (int c = 0; c < 4; c++) {
            const int cc = (c + arot) & 3;
            cpa16(sA[s] + (uint32_t)(lm * AST + cc * 4) * 4, asrc + cc * 4, asz);
        }
#pragma unroll
        for (int c = 0; c < 4; c++) {
            const int k = c * 4 + bw;
            cpa16(sB[s] + (uint32_t)(k * BST + bn) * 4,
                  bbase + (size_t)(k0 + k) * ldb + bn, 16);
        }
    };

    load_stage(0, 0);
    cpa_commit();

    const int rb = wm + (lane >> 2);
    const int cb = wn + (lane >> 2);
    const int kq = lane & 3;

    for (int t = 0; t < nt; t++) {
        cpa_wait0();
        __syncthreads();
        if (t + 1 < nt) load_stage((t + 1) & 1, (t + 1) * 16);
        cpa_commit();

        const int buf = t & 1;
#pragma unroll
        for (int ks = 0; ks < 2; ks++) {
            const int kk = ks * 8 + kq;
            uint32_t af[4][4], bf[8][2];
#pragma unroll
            for (int i = 0; i < 4; i++) {
                af[i][0] = __float_as_uint(As[buf][rb + i * 16][kk]);
                af[i][1] = __float_as_uint(As[buf][rb + i * 16 + 8][kk]);
                af[i][2] = __float_as_uint(As[buf][rb + i * 16][kk + 4]);
                af[i][3] = __float_as_uint(As[buf][rb + i * 16 + 8][kk + 4]);
            }
#pragma unroll
            for (int j = 0; j < 8; j++) {
                bf[j][0] = __float_as_uint(Bs[buf][kk][cb + j * 8]);
                bf[j][1] = __float_as_uint(Bs[buf][kk + 4][cb + j * 8]);
            }
#pragma unroll
            for (int i = 0; i < 4; i++)
#pragma unroll
                for (int j = 0; j < 8; j++)
                    mma_tf32(acc[i][j], af[i], bf[j]);
        }
        __syncthreads();
    }

    // ---------------- epilogues ----------------
    const float scl = 0.08838834764831845f;  // 1/sqrt(128)
    constexpr bool RND = (MODE==GM_V || MODE==GM_PV);   // outputs feeding a GEMM directly
#pragma unroll
    for (int i = 0; i < 4; i++) {
#pragma unroll
        for (int rr = 0; rr < 2; rr++) {
            const int r = m0 + wm + i * 16 + (lane >> 2) + rr * 8;
            if (r >= Mz) continue;
            if (MODE==GM_SCORES) {
                const size_t base = (size_t)z * Sc * Sc + (size_t)r * Sc;
#pragma unroll
                for (int j = 0; j < 8; j++) {
                    const int c = n0 + wn + j * 8 + (lane & 3) * 2;
                    float v0 = acc[i][j][rr * 2 + 0] * scl;
                    float v1 = acc[i][j][rr * 2 + 1] * scl;
                    if (c > r)     v0 = -1e9f;
                    if (c + 1 > r) v1 = -1e9f;
                    g_sc[base + c]     = v0;
                    g_sc[base + c + 1] = v1;
                }
            } else if (MODE==GM_MD) {
                const int tok = g_list[z * Tc + r];
                const float w = g_dw[tok * Ec + z];
                float* dst = g_moe + (size_t)tok * 2048;
#pragma unroll
                for (int j = 0; j < 8; j++) {
                    const int c = n0 + wn + j * 8 + (lane & 3) * 2;
                    atomicAdd(dst + c,     acc[i][j][rr * 2 + 0] * w);
                    atomicAdd(dst + c + 1, acc[i][j][rr * 2 + 1] * w);
                }
            } else {
                float* Cp; int ldc; const float* bias = nullptr; const float* res = nullptr;
                if (MODE==GM_Q)       { Cp = g_q;  ldc = 2048; bias = extra; }
                else if (MODE==GM_K)  { Cp = g_k;  ldc = 256;  bias = extra; }
                else if (MODE==GM_V)  { Cp = g_v;  ldc = 256;  bias = extra; }
                else if (MODE==GM_PV) { Cp = g_ao + (size_t)bb * Sc * 2048 + hh * 128; ldc = 2048; }
                else if (MODE==GM_O)  { Cp = g_x;  ldc = 2048; res = extra; }
                else if (MODE==GM_MG) { Cp = g_mg + (size_t)z * Tc * IM; ldc = IM; }
                else if (MODE==GM_MU) { Cp = g_mu + (size_t)z * Tc * IM; ldc = IM; }
                else if (MODE==GM_SG) { Cp = g_sgv; ldc = ISH; }
                else if (MODE==GM_SU) { Cp = g_suv; ldc = ISH; }
                else                  { Cp = g_sh;  ldc = 2048; }
                const size_t rowoff = (size_t)r * ldc;
#pragma unroll
                for (int j = 0; j < 8; j++) {
                    const int c = n0 + wn + j * 8 + (lane & 3) * 2;
                    float v0 = acc[i][j][rr * 2 + 0];
                    float v1 = acc[i][j][rr * 2 + 1];
                    if (bias) { v0 += bias[c]; v1 += bias[c + 1]; }
                    if (res)  { v0 += res[rowoff + c]; v1 += res[rowoff + c + 1]; }
                    if (RND)  { v0 = tf32r(v0); v1 = tf32r(v1); }
                    Cp[rowoff + c]     = v0;
                    Cp[rowoff + c + 1] = v1;
                }
            }
        }
    }
}

// ---------------- launch ----------------
extern "C" void kernel_launch(void* const* d_in, const int* in_sizes, int n_in,
                              void* d_out, int out_size) {
    (void)in_sizes; (void)n_in; (void)out_size;
    const float* x0  = (const float*)d_in[0];
    const float* ln1 = (const float*)d_in[1];
    const float* wq  = (const float*)d_in[2];
    const float* bq  = (const float*)d_in[3];
    const float* wk  = (const float*)d_in[4];
    const float* bk  = (const float*)d_in[5];
    const float* wv  = (const float*)d_in[6];
    const float* bv  = (const float*)d_in[7];
    const float* wo  = (const float*)d_in[8];
    const float* ln2 = (const float*)d_in[9];
    const float* rw  = (const float*)d_in[10];
    const float* wg  = (const float*)d_in[11];
    const float* wu  = (const float*)d_in[12];
    const float* wd  = (const float*)d_in[13];
    const float* swg = (const float*)d_in[14];
    const float* swu = (const float*)d_in[15];
    const float* swd = (const float*)d_in[16];
    const float* sgw = (const float*)d_in[17];
    float* out = (float*)d_out;

    auto blocks = [](size_t n) { return (unsigned)((n + 255) / 256); };

    // tf32-round all weights into scratch
    round_copy_kernel<OFF_WQ ><<<blocks((size_t)2048*2048), 256>>>(wq,  2048*2048);
    round_copy_kernel<OFF_WK ><<<blocks((size_t)2048*256),  256>>>(wk,  2048*256);
    round_copy_kernel<OFF_WV ><<<blocks((size_t)2048*256),  256>>>(wv,  2048*256);
    round_copy_kernel<OFF_WO ><<<blocks((size_t)2048*2048), 256>>>(wo,  2048*2048);
    round_copy_kernel<OFF_WG ><<<blocks((size_t)Ec*2048*IM),256>>>(wg,  Ec*2048*IM);
    round_copy_kernel<OFF_WU ><<<blocks((size_t)Ec*2048*IM),256>>>(wu,  Ec*2048*IM);
    round_copy_kernel<OFF_WD ><<<blocks((size_t)Ec*IM*2048),256>>>(wd,  Ec*IM*2048);
    round_copy_kernel<OFF_SWG><<<blocks((size_t)2048*ISH),  256>>>(swg, 2048*ISH);
    round_copy_kernel<OFF_SWU><<<blocks((size_t)2048*ISH),  256>>>(swu, 2048*ISH);
    round_copy_kernel<OFF_SWD><<<blocks((size_t)ISH*2048),  256>>>(swd, ISH*2048);

    clear_cnt_kernel<<<1, 32>>>();
    clear_moe_kernel<<<(Tc * Hc) / 256, 256>>>();

    // attention
    rmsnorm_kernel<0><<<Tc, 256>>>(x0, ln1);
    gemm_kernel<GM_Q><<<dim3(16, 32, 1), 128>>>(bq);
    gemm_kernel<GM_K><<<dim3(2, 32, 1), 128>>>(bk);
    gemm_kernel<GM_V><<<dim3(2, 32, 1), 128>>>(bv);
    rope_kernel<<<dim3(Tc, NQc + NKVc), 64>>>();
    kT_kernel<<<(Bc * NKVc * DHc * Sc) / 256, 256>>>();
    gemm_kernel<GM_SCORES><<<dim3(16, 16, 32), 128>>>(nullptr);
    softmax_kernel<<<Bc * NQc * Sc, 256>>>();
    gemm_kernel<GM_PV><<<dim3(1, 16, 32), 128>>>(nullptr);
    gemm_kernel<GM_O><<<dim3(16, 32, 1), 128>>>(x0);

    // MoE block
    rmsnorm_kernel<1><<<Tc, 256>>>(nullptr, ln2);
    router_kernel<<<Tc / 8, 256>>>(rw);
    gemm_kernel<GM_MG><<<dim3(11, 32, 8), 128>>>(nullptr);
    gemm_kernel<GM_MU><<<dim3(11, 32, 8), 128>>>(nullptr);
    moe_act_kernel<<<dim3(6, Tc, 8), 256>>>();
    gemm_kernel<GM_MD><<<dim3(16, 32, 8), 128>>>(nullptr);

    // shared expert
    gemm_kernel<GM_SG><<<dim3(44, 32, 1), 128>>>(nullptr);
    gemm_kernel<GM_SU><<<dim3(44, 32, 1), 128>>>(nullptr);
    shared_act_kernel<<<(size_t)(Tc) * ISH / 256, 256>>>();
    sgate_kernel<<<Tc / 8, 256>>>(sgw);
    gemm_kernel<GM_SD><<<dim3(16, 32, 1), 128>>>(nullptr);

    final_kernel<<<(Tc * Hc) / 256, 256>>>(out);
}